// round 2
// baseline (speedup 1.0000x reference)
#include <cuda_runtime.h>
#include <cuda_bf16.h>
#include <math.h>

// Problem constants (fixed shapes per reference)
#define NN 100000
#define BB 1024
#define LAT 128
#define INDIM 384      // NODE_DIM + 2*LATENT
#define FFNIN 512      // LATENT + IN_DIM
#define CAP 2048       // neighbor list capacity (expected ~50/row)

// Scratch (device globals; no allocation allowed)
__device__ float g_qin[BB * INDIM];    // q_input, reused in epilogue concat
__device__ float g_qk[BB * INDIM];     // Wk^T q  per query
__device__ float g_qbias[BB];          // q . bk  per query
__device__ float g_acc[BB * INDIM];    // softmax-weighted sum of kv rows
__device__ unsigned g_sig[4];          // dtype signature counters

#define MODE_U8   0
#define MODE_I32  1
#define MODE_F32  2
#define MODE_BF16 3

// ---------------------------------------------------------------------------
// Mask-dtype probe: scan first 4MB (valid for every candidate dtype) and count
// signature patterns. bool mask may have been coerced to f32/i32/bf16.
//   g_sig[0] = # words == 0x3F800000  (f32 1.0; also bf16 1.0 in high half)
//   g_sig[1] = # words == 0x00003F80  (bf16 1.0 in low half; unique to bf16)
//   g_sig[2] = # words == 0x00000001  (i32 1; also u8 1 at aligned offset)
//   g_sig[3] = # bytes == 0x01        (u8 gives ~4x the i32 count)
// ---------------------------------------------------------------------------
__global__ void k_sig_zero() {
    if (threadIdx.x < 4) g_sig[threadIdx.x] = 0u;
}

__global__ void __launch_bounds__(256) k_sig_probe(const unsigned* __restrict__ w)
{
    unsigned c0 = 0, c1 = 0, c2 = 0, c3 = 0;
    int stride = gridDim.x * blockDim.x;
    for (int i = blockIdx.x * blockDim.x + threadIdx.x; i < (1 << 20); i += stride) {
        unsigned v = w[i];
        if (v == 0u) continue;
        c0 += (v == 0x3F800000u);
        c1 += (v == 0x00003F80u);
        c2 += (v == 0x00000001u);
        #pragma unroll
        for (int bb = 0; bb < 4; bb++) c3 += (((v >> (bb * 8)) & 0xFFu) == 0x01u);
    }
    // warp reduce then atomic
    #pragma unroll
    for (int o = 16; o; o >>= 1) {
        c0 += __shfl_down_sync(0xffffffffu, c0, o);
        c1 += __shfl_down_sync(0xffffffffu, c1, o);
        c2 += __shfl_down_sync(0xffffffffu, c2, o);
        c3 += __shfl_down_sync(0xffffffffu, c3, o);
    }
    if ((threadIdx.x & 31) == 0) {
        if (c0) atomicAdd(&g_sig[0], c0);
        if (c1) atomicAdd(&g_sig[1], c1);
        if (c2) atomicAdd(&g_sig[2], c2);
        if (c3) atomicAdd(&g_sig[3], c3);
    }
}

// ---------------------------------------------------------------------------
// Kernel 1: per-query prep. 1024 blocks x 128 threads.
//   q_input[b] = [x[idx], memory[idx], tar_t[b]]
//   q[b]  = Wq @ q_input + bq
//   qk[b] = Wk^T @ q[b]          (edge score = qk . kv + q.bk)
// ---------------------------------------------------------------------------
__global__ void __launch_bounds__(128) k_prep(
    const float* __restrict__ x, const float* __restrict__ mem,
    const float* __restrict__ tart, const int* __restrict__ tar_idx,
    const float* __restrict__ Wq, const float* __restrict__ bq,
    const float* __restrict__ Wk, const float* __restrict__ bk)
{
    int b = blockIdx.x;
    int t = threadIdx.x;
    __shared__ float qin[INDIM];
    __shared__ float q[LAT];
    __shared__ float red[4];

    int idx = tar_idx[b];
    qin[t]         = x[(size_t)idx * LAT + t];
    qin[LAT + t]   = mem[(size_t)idx * LAT + t];
    qin[2*LAT + t] = tart[b * LAT + t];
    __syncthreads();

    g_qin[b * INDIM + t]         = qin[t];
    g_qin[b * INDIM + LAT + t]   = qin[LAT + t];
    g_qin[b * INDIM + 2*LAT + t] = qin[2*LAT + t];

    {
        const float* wr = Wq + (size_t)t * INDIM;
        float s = bq[t];
        #pragma unroll 8
        for (int j = 0; j < INDIM; j++) s = fmaf(wr[j], qin[j], s);
        q[t] = s;
    }
    __syncthreads();

    {
        float a0 = 0.f, a1 = 0.f, a2 = 0.f;
        for (int j = 0; j < LAT; j++) {
            float qj = q[j];
            const float* wr = Wk + (size_t)j * INDIM;
            a0 = fmaf(qj, wr[t],       a0);
            a1 = fmaf(qj, wr[t + 128], a1);
            a2 = fmaf(qj, wr[t + 256], a2);
        }
        g_qk[b * INDIM + t]       = a0;
        g_qk[b * INDIM + t + 128] = a1;
        g_qk[b * INDIM + t + 256] = a2;
    }

    {
        float v = q[t] * bk[t];
        #pragma unroll
        for (int o = 16; o; o >>= 1) v += __shfl_down_sync(0xffffffffu, v, o);
        if ((t & 31) == 0) red[t >> 5] = v;
        __syncthreads();
        if (t == 0) g_qbias[b] = red[0] + red[1] + red[2] + red[3];
    }
}

// ---------------------------------------------------------------------------
// Kernel 2: sparse attention. One block (256 thr / 8 warps) per query.
// ---------------------------------------------------------------------------
__global__ void __launch_bounds__(256) k_attn(
    const float* __restrict__ x, const float* __restrict__ mem,
    const float* __restrict__ dt, const unsigned char* __restrict__ maskb,
    const int* __restrict__ tar_idx)
{
    int b = blockIdx.x;
    int t = threadIdx.x;
    int lane = t & 31;
    int w = t >> 5;

    __shared__ int   s_idx[CAP];
    __shared__ float s_sc[CAP];
    __shared__ float s_qk[INDIM];
    __shared__ float s_part[8 * INDIM];
    __shared__ float s_red[8];
    __shared__ int   s_cnt;
    __shared__ float s_m, s_l;

    if (t == 0) s_cnt = 0;
    for (int c = t; c < INDIM; c += 256) s_qk[c] = g_qk[b * INDIM + c];

    // decide mask dtype from probe signature (cheap, every thread)
    unsigned c_f32 = g_sig[0], c_bf16 = g_sig[1], c_i32 = g_sig[2], c_u8 = g_sig[3];
    int mode;
    if (c_bf16 > 0)            mode = MODE_BF16;
    else if (c_f32 > 0)        mode = MODE_F32;
    else if (c_u8 > 2 * c_i32) mode = MODE_U8;
    else                       mode = MODE_I32;
    __syncthreads();

    // ---- 1) mask scan, compact neighbor indices ----
    if (mode == MODE_U8) {
        const uint4* row = (const uint4*)(maskb + (size_t)b * NN);
        for (int i = t; i < NN / 16; i += 256) {
            uint4 u = row[i];
            if (u.x | u.y | u.z | u.w) {
                unsigned vals[4] = {u.x, u.y, u.z, u.w};
                #pragma unroll
                for (int k2 = 0; k2 < 4; k2++) {
                    unsigned v = vals[k2];
                    if (!v) continue;
                    #pragma unroll
                    for (int bb = 0; bb < 4; bb++) {
                        if ((v >> (bb * 8)) & 0xFFu) {
                            int slot = atomicAdd(&s_cnt, 1);
                            if (slot < CAP) s_idx[slot] = i * 16 + k2 * 4 + bb;
                        }
                    }
                }
            }
        }
    } else if (mode == MODE_I32 || mode == MODE_F32) {
        const uint4* row = (const uint4*)(maskb + (size_t)b * NN * 4);
        for (int i = t; i < NN / 4; i += 256) {
            uint4 u = row[i];
            if (u.x | u.y | u.z | u.w) {
                unsigned vals[4] = {u.x, u.y, u.z, u.w};
                #pragma unroll
                for (int k2 = 0; k2 < 4; k2++) {
                    if (vals[k2]) {
                        int slot = atomicAdd(&s_cnt, 1);
                        if (slot < CAP) s_idx[slot] = i * 4 + k2;
                    }
                }
            }
        }
    } else { // MODE_BF16
        const uint4* row = (const uint4*)(maskb + (size_t)b * NN * 2);
        for (int i = t; i < NN / 8; i += 256) {
            uint4 u = row[i];
            if (u.x | u.y | u.z | u.w) {
                unsigned vals[4] = {u.x, u.y, u.z, u.w};
                #pragma unroll
                for (int k2 = 0; k2 < 4; k2++) {
                    unsigned v = vals[k2];
                    if (v & 0xFFFFu) {
                        int slot = atomicAdd(&s_cnt, 1);
                        if (slot < CAP) s_idx[slot] = i * 8 + k2 * 2;
                    }
                    if (v >> 16) {
                        int slot = atomicAdd(&s_cnt, 1);
                        if (slot < CAP) s_idx[slot] = i * 8 + k2 * 2 + 1;
                    }
                }
            }
        }
    }
    __syncthreads();
    if (s_cnt == 0 && t == 0) { s_idx[0] = tar_idx[b]; s_cnt = 1; }
    __syncthreads();
    int cnt = min(s_cnt, CAP);

    // ---- 2) scores: warp w handles edges w, w+8, ... ----
    float qb = g_qbias[b];
    const float scale = 0.08838834764831845f;   // 1/sqrt(128)
    for (int p = w; p < cnt; p += 8) {
        int n = s_idx[p];
        const float* px = x   + (size_t)n * LAT;
        const float* pm = mem + (size_t)n * LAT;
        const float* pd = dt  + (size_t)n * LAT;
        float dot = 0.f;
        #pragma unroll
        for (int r = 0; r < 4; r++) dot = fmaf(px[lane + 32*r], s_qk[lane + 32*r], dot);
        #pragma unroll
        for (int r = 0; r < 4; r++) dot = fmaf(pm[lane + 32*r], s_qk[128 + lane + 32*r], dot);
        #pragma unroll
        for (int r = 0; r < 4; r++) dot = fmaf(pd[lane + 32*r], s_qk[256 + lane + 32*r], dot);
        #pragma unroll
        for (int o = 16; o; o >>= 1) dot += __shfl_down_sync(0xffffffffu, dot, o);
        if (lane == 0) s_sc[p] = (dot + qb) * scale;
    }
    __syncthreads();

    // ---- 3) softmax ----
    {
        float lm = -INFINITY;
        for (int p = t; p < cnt; p += 256) lm = fmaxf(lm, s_sc[p]);
        #pragma unroll
        for (int o = 16; o; o >>= 1) lm = fmaxf(lm, __shfl_xor_sync(0xffffffffu, lm, o));
        if (lane == 0) s_red[w] = lm;
        __syncthreads();
        if (t == 0) {
            float m = s_red[0];
            #pragma unroll
            for (int i = 1; i < 8; i++) m = fmaxf(m, s_red[i]);
            s_m = m;
        }
        __syncthreads();
    }
    float m = s_m;
    {
        float ls = 0.f;
        for (int p = t; p < cnt; p += 256) {
            float e = __expf(s_sc[p] - m);
            s_sc[p] = e;
            ls += e;
        }
        #pragma unroll
        for (int o = 16; o; o >>= 1) ls += __shfl_xor_sync(0xffffffffu, ls, o);
        if (lane == 0) s_red[w] = ls;
        __syncthreads();
        if (t == 0) {
            float l = 0.f;
            #pragma unroll
            for (int i = 0; i < 8; i++) l += s_red[i];
            s_l = l;
        }
        __syncthreads();
    }
    float inv = 1.f / s_l;

    // ---- 4) weighted kv accumulation ----
    float racc[12];
    #pragma unroll
    for (int r = 0; r < 12; r++) racc[r] = 0.f;
    for (int p = w; p < cnt; p += 8) {
        int n = s_idx[p];
        float wgt = s_sc[p] * inv;
        const float* px = x   + (size_t)n * LAT;
        const float* pm = mem + (size_t)n * LAT;
        const float* pd = dt  + (size_t)n * LAT;
        #pragma unroll
        for (int r = 0; r < 4; r++) racc[r]     = fmaf(wgt, px[lane + 32*r], racc[r]);
        #pragma unroll
        for (int r = 0; r < 4; r++) racc[4 + r] = fmaf(wgt, pm[lane + 32*r], racc[4 + r]);
        #pragma unroll
        for (int r = 0; r < 4; r++) racc[8 + r] = fmaf(wgt, pd[lane + 32*r], racc[8 + r]);
    }
    #pragma unroll
    for (int r = 0; r < 12; r++) s_part[w * INDIM + 32*r + lane] = racc[r];
    __syncthreads();
    for (int c = t; c < INDIM; c += 256) {
        float s = 0.f;
        #pragma unroll
        for (int ww = 0; ww < 8; ww++) s += s_part[ww * INDIM + c];
        g_acc[b * INDIM + c] = s;
    }
}

// ---------------------------------------------------------------------------
// Kernel 3: epilogue. 1024 blocks x 128 threads.
// ---------------------------------------------------------------------------
__global__ void __launch_bounds__(128) k_epi(
    const float* __restrict__ Wv, const float* __restrict__ bv,
    const float* __restrict__ W1, const float* __restrict__ b1,
    const float* __restrict__ W2, const float* __restrict__ b2,
    float* __restrict__ out)
{
    int b = blockIdx.x;
    int t = threadIdx.x;
    __shared__ float acc[INDIM];
    __shared__ float z[FFNIN];
    __shared__ float h[LAT];

    for (int c = t; c < INDIM; c += 128) {
        acc[c] = g_acc[b * INDIM + c];
        z[LAT + c] = g_qin[b * INDIM + c];
    }
    __syncthreads();

    {
        const float* wr = Wv + (size_t)t * INDIM;
        float a = bv[t];
        #pragma unroll 8
        for (int j = 0; j < INDIM; j++) a = fmaf(wr[j], acc[j], a);
        z[t] = a;
    }
    __syncthreads();

    {
        const float* wr = W1 + (size_t)t * FFNIN;
        float s = b1[t];
        #pragma unroll 8
        for (int j = 0; j < FFNIN; j++) s = fmaf(wr[j], z[j], s);
        h[t] = fmaxf(s, 0.f);
    }
    __syncthreads();

    {
        const float* wr = W2 + (size_t)t * LAT;
        float s = b2[t];
        #pragma unroll 8
        for (int j = 0; j < LAT; j++) s = fmaf(wr[j], h[j], s);
        out[b * LAT + t] = s;
    }
}

// ---------------------------------------------------------------------------
extern "C" void kernel_launch(void* const* d_in, const int* in_sizes, int n_in,
                              void* d_out, int out_size)
{
    const float* x    = (const float*)d_in[0];
    const float* mem  = (const float*)d_in[1];
    const float* dt   = (const float*)d_in[2];
    const float* tart = (const float*)d_in[3];
    const unsigned char* mask = (const unsigned char*)d_in[4];
    const int*   tidx = (const int*)d_in[5];
    const float* Wq = (const float*)d_in[6];
    const float* bq = (const float*)d_in[7];
    const float* Wk = (const float*)d_in[8];
    const float* bk = (const float*)d_in[9];
    const float* Wv = (const float*)d_in[10];
    const float* bv = (const float*)d_in[11];
    const float* W1 = (const float*)d_in[12];
    const float* b1 = (const float*)d_in[13];
    const float* W2 = (const float*)d_in[14];
    const float* b2 = (const float*)d_in[15];
    float* out = (float*)d_out;

    k_sig_zero<<<1, 32>>>();
    k_sig_probe<<<128, 256>>>((const unsigned*)mask);
    k_prep<<<BB, 128>>>(x, mem, tart, tidx, Wq, bq, Wk, bk);
    k_attn<<<BB, 256>>>(x, mem, dt, mask, tidx);
    k_epi<<<BB, 128>>>(Wv, bv, W1, b1, W2, b2, out);
}

// round 3
// speedup vs baseline: 4.7483x; 4.7483x over previous
#include <cuda_runtime.h>
#include <math.h>

// Problem constants (fixed shapes per reference)
#define NN 100000
#define BB 1024
#define LAT 128
#define INDIM 384      // NODE_DIM + 2*LATENT
#define FFNIN 512      // LATENT + IN_DIM
#define CAP 512        // neighbor list capacity (mean ~50, 512 = ~65 sigma)
#define GQ 8           // queries per block in prep/epi

// Scratch (device globals; no allocation allowed)
__device__ float g_qin[BB * INDIM];
__device__ float g_qk[BB * INDIM];
__device__ float g_qbias[BB];
__device__ float g_acc[BB * INDIM];
__device__ int   g_list[BB * CAP];
__device__ int   g_cnt[BB];
__device__ unsigned g_sig[4];

// ---------------------------------------------------------------------------
// Mask-dtype probe (unchanged from R2 — it worked)
// ---------------------------------------------------------------------------
__global__ void k_sig_zero() {
    if (threadIdx.x < 4) g_sig[threadIdx.x] = 0u;
}

__global__ void __launch_bounds__(256) k_sig_probe(const unsigned* __restrict__ w)
{
    unsigned c0 = 0, c1 = 0, c2 = 0, c3 = 0;
    int stride = gridDim.x * blockDim.x;
    for (int i = blockIdx.x * blockDim.x + threadIdx.x; i < (1 << 20); i += stride) {
        unsigned v = w[i];
        if (v == 0u) continue;
        c0 += (v == 0x3F800000u);
        c1 += (v == 0x00003F80u);
        c2 += (v == 0x00000001u);
        #pragma unroll
        for (int bb = 0; bb < 4; bb++) c3 += (((v >> (bb * 8)) & 0xFFu) == 0x01u);
    }
    #pragma unroll
    for (int o = 16; o; o >>= 1) {
        c0 += __shfl_down_sync(0xffffffffu, c0, o);
        c1 += __shfl_down_sync(0xffffffffu, c1, o);
        c2 += __shfl_down_sync(0xffffffffu, c2, o);
        c3 += __shfl_down_sync(0xffffffffu, c3, o);
    }
    if ((threadIdx.x & 31) == 0) {
        if (c0) atomicAdd(&g_sig[0], c0);
        if (c1) atomicAdd(&g_sig[1], c1);
        if (c2) atomicAdd(&g_sig[2], c2);
        if (c3) atomicAdd(&g_sig[3], c3);
    }
}

// ---------------------------------------------------------------------------
// Kernel 1: prep. 128 blocks x 512 threads, GQ=8 queries per block.
//   gather q_input; q = Wq@qin + bq (coalesced warp-per-output);
//   qbias = q.bk ; qk = Wk^T q (smem-staged Wk tiles, coalesced)
// ---------------------------------------------------------------------------
__global__ void __launch_bounds__(512) k_prep(
    const float* __restrict__ x, const float* __restrict__ mem,
    const float* __restrict__ tart, const int* __restrict__ tidx,
    const float* __restrict__ Wq, const float* __restrict__ bq,
    const float* __restrict__ Wk, const float* __restrict__ bk)
{
    int b0 = blockIdx.x * GQ;
    int t = threadIdx.x, lane = t & 31, w = t >> 5;
    __shared__ float qin[GQ][INDIM];
    __shared__ float qsm[GQ][LAT];
    __shared__ float wk_sm[16][INDIM];
    __shared__ int sidx[GQ];

    if (t < GQ) sidx[t] = tidx[b0 + t];
    __syncthreads();

    // gather q_input (float4, coalesced) + persist to global
    for (int m = t; m < GQ * 96; m += 512) {
        int q = m / 96, c4 = m % 96;
        float4 v;
        if (c4 < 32)      v = ((const float4*)(x    + (size_t)sidx[q] * LAT))[c4];
        else if (c4 < 64) v = ((const float4*)(mem  + (size_t)sidx[q] * LAT))[c4 - 32];
        else              v = ((const float4*)(tart + (size_t)(b0 + q) * LAT))[c4 - 64];
        *(float4*)&qin[q][c4 * 4] = v;
        *(float4*)&g_qin[(size_t)(b0 + q) * INDIM + c4 * 4] = v;
    }
    __syncthreads();

    // q = Wq @ qin + bq : 16 warps x 8 outputs, W row cached in regs, reused over 8 queries
    for (int oi = 0; oi < 8; oi++) {
        int o = w * 8 + oi;
        const float* wr = Wq + (size_t)o * INDIM;
        float wreg[12];
        #pragma unroll
        for (int r = 0; r < 12; r++) wreg[r] = wr[lane + 32 * r];
        float p[GQ];
        #pragma unroll
        for (int q = 0; q < GQ; q++) {
            float s = 0.f;
            #pragma unroll
            for (int r = 0; r < 12; r++) s = fmaf(wreg[r], qin[q][lane + 32 * r], s);
            #pragma unroll
            for (int off = 16; off; off >>= 1) s += __shfl_xor_sync(0xffffffffu, s, off);
            p[q] = s;
        }
        float val = p[0];
        #pragma unroll
        for (int q = 1; q < GQ; q++) if (lane == q) val = p[q];
        if (lane < GQ) qsm[lane][o] = val + bq[o];
    }
    __syncthreads();

    // qbias[q] = q . bk  (warp w -> query w)
    if (w < GQ) {
        float v = 0.f;
        #pragma unroll
        for (int r = 0; r < 4; r++) v = fmaf(qsm[w][lane + 32 * r], bk[lane + 32 * r], v);
        #pragma unroll
        for (int off = 16; off; off >>= 1) v += __shfl_xor_sync(0xffffffffu, v, off);
        if (lane == 0) g_qbias[b0 + w] = v;
    }

    // qk[q][c] = sum_j qsm[q][j] * Wk[j][c]  (stage Wk in 16-row smem tiles)
    float acc[GQ];
    #pragma unroll
    for (int q = 0; q < GQ; q++) acc[q] = 0.f;
    for (int j0 = 0; j0 < LAT; j0 += 16) {
        __syncthreads();
        for (int m = t; m < 16 * 96; m += 512) {
            int jj = m / 96, c4 = m % 96;
            *(float4*)&wk_sm[jj][c4 * 4] =
                ((const float4*)(Wk + (size_t)(j0 + jj) * INDIM))[c4];
        }
        __syncthreads();
        if (t < INDIM) {
            #pragma unroll
            for (int jj = 0; jj < 16; jj++) {
                float wv = wk_sm[jj][t];
                #pragma unroll
                for (int q = 0; q < GQ; q++) acc[q] = fmaf(qsm[q][j0 + jj], wv, acc[q]);
            }
        }
    }
    if (t < INDIM) {
        #pragma unroll
        for (int q = 0; q < GQ; q++) g_qk[(size_t)(b0 + q) * INDIM + t] = acc[q];
    }
}

// ---------------------------------------------------------------------------
// Kernel 2: mask scan -> edge lists. 1024 blocks x 256 thr. Low regs, MLP=4.
// ---------------------------------------------------------------------------
#define PROC4(u, base) \
    if (u.x | u.y | u.z | u.w) { \
        if (u.x) { int sl = atomicAdd(&s_cnt, 1); if (sl < CAP) s_idx[sl] = (base) * 4 + 0; } \
        if (u.y) { int sl = atomicAdd(&s_cnt, 1); if (sl < CAP) s_idx[sl] = (base) * 4 + 1; } \
        if (u.z) { int sl = atomicAdd(&s_cnt, 1); if (sl < CAP) s_idx[sl] = (base) * 4 + 2; } \
        if (u.w) { int sl = atomicAdd(&s_cnt, 1); if (sl < CAP) s_idx[sl] = (base) * 4 + 3; } }

__global__ void __launch_bounds__(256) k_scan(
    const unsigned char* __restrict__ maskb, const int* __restrict__ tidx)
{
    int b = blockIdx.x, t = threadIdx.x;
    __shared__ int s_idx[CAP];
    __shared__ int s_cnt;
    if (t == 0) s_cnt = 0;
    unsigned c_f32 = g_sig[0], c_bf16 = g_sig[1], c_i32 = g_sig[2], c_u8 = g_sig[3];
    int mode = (c_bf16 > 0) ? 3 : (c_f32 > 0) ? 2 : (c_u8 > 2 * c_i32) ? 0 : 1;
    __syncthreads();

    if (mode == 1 || mode == 2) {                 // 4-byte elements (i32/f32)
        const uint4* row = (const uint4*)(maskb + (size_t)b * NN * 4);
        const int NW = NN / 4;                    // 25000 uint4
        int i = t;
        for (; i + 768 < NW; i += 1024) {
            uint4 a = row[i], b4 = row[i + 256], c4 = row[i + 512], d4 = row[i + 768];
            PROC4(a, i) PROC4(b4, i + 256) PROC4(c4, i + 512) PROC4(d4, i + 768)
        }
        for (; i < NW; i += 256) { uint4 u = row[i]; PROC4(u, i) }
    } else if (mode == 0) {                       // u8
        const uint4* row = (const uint4*)(maskb + (size_t)b * NN);
        for (int i = t; i < NN / 16; i += 256) {
            uint4 u = row[i];
            if (u.x | u.y | u.z | u.w) {
                unsigned vals[4] = {u.x, u.y, u.z, u.w};
                #pragma unroll
                for (int k2 = 0; k2 < 4; k2++) {
                    unsigned v = vals[k2];
                    if (!v) continue;
                    #pragma unroll
                    for (int bb = 0; bb < 4; bb++) {
                        if ((v >> (bb * 8)) & 0xFFu) {
                            int sl = atomicAdd(&s_cnt, 1);
                            if (sl < CAP) s_idx[sl] = i * 16 + k2 * 4 + bb;
                        }
                    }
                }
            }
        }
    } else {                                      // bf16
        const uint4* row = (const uint4*)(maskb + (size_t)b * NN * 2);
        for (int i = t; i < NN / 8; i += 256) {
            uint4 u = row[i];
            if (u.x | u.y | u.z | u.w) {
                unsigned vals[4] = {u.x, u.y, u.z, u.w};
                #pragma unroll
                for (int k2 = 0; k2 < 4; k2++) {
                    unsigned v = vals[k2];
                    if (v & 0xFFFFu) { int sl = atomicAdd(&s_cnt, 1); if (sl < CAP) s_idx[sl] = i * 8 + k2 * 2; }
                    if (v >> 16)     { int sl = atomicAdd(&s_cnt, 1); if (sl < CAP) s_idx[sl] = i * 8 + k2 * 2 + 1; }
                }
            }
        }
    }
    __syncthreads();
    int cnt = min(s_cnt, CAP);
    if (cnt == 0) {
        if (t == 0) { g_list[b * CAP] = tidx[b]; g_cnt[b] = 1; }
        return;
    }
    for (int m = t; m < cnt; m += 256) g_list[b * CAP + m] = s_idx[m];
    if (t == 0) g_cnt[b] = cnt;
}

// ---------------------------------------------------------------------------
// Kernel 3: gather + single-pass online-softmax attention. 1024 blocks x 256.
// Each neighbor row is loaded ONCE: same registers feed score dot and
// weighted accumulation.
// ---------------------------------------------------------------------------
__global__ void __launch_bounds__(256) k_gather(
    const float* __restrict__ x, const float* __restrict__ mem,
    const float* __restrict__ dt)
{
    int b = blockIdx.x, t = threadIdx.x, lane = t & 31, w = t >> 5;
    __shared__ float s_qk[INDIM];
    __shared__ float s_part[8][INDIM];
    __shared__ float s_m[8], s_l[8];

    for (int c = t; c < INDIM; c += 256) s_qk[c] = g_qk[(size_t)b * INDIM + c];
    __syncthreads();
    int cnt = g_cnt[b];
    float qb = g_qbias[b];
    const float scale = 0.08838834764831845f;   // 1/sqrt(128)

    float m = -INFINITY, l = 0.f;
    float racc[12];
    #pragma unroll
    for (int r = 0; r < 12; r++) racc[r] = 0.f;

    for (int p = w; p < cnt; p += 8) {
        int n = g_list[b * CAP + p];
        const float* px = x   + (size_t)n * LAT;
        const float* pm = mem + (size_t)n * LAT;
        const float* pd = dt  + (size_t)n * LAT;
        float rowv[12];
        #pragma unroll
        for (int r = 0; r < 4; r++) rowv[r]     = px[lane + 32 * r];
        #pragma unroll
        for (int r = 0; r < 4; r++) rowv[4 + r] = pm[lane + 32 * r];
        #pragma unroll
        for (int r = 0; r < 4; r++) rowv[8 + r] = pd[lane + 32 * r];
        float dot = 0.f;
        #pragma unroll
        for (int r = 0; r < 12; r++) dot = fmaf(rowv[r], s_qk[32 * r + lane], dot);
        #pragma unroll
        for (int off = 16; off; off >>= 1) dot += __shfl_xor_sync(0xffffffffu, dot, off);
        float s = (dot + qb) * scale;
        float mnew = fmaxf(m, s);
        float corr = __expf(m - mnew);          // 0 on first edge (m=-inf)
        float e = __expf(s - mnew);
        l = l * corr + e;
        m = mnew;
        #pragma unroll
        for (int r = 0; r < 12; r++) racc[r] = fmaf(racc[r], corr, e * rowv[r]);
    }
    #pragma unroll
    for (int r = 0; r < 12; r++) s_part[w][32 * r + lane] = racc[r];
    if (lane == 0) { s_m[w] = m; s_l[w] = l; }
    __syncthreads();

    // merge 8 warp-local online-softmax states
    float M = s_m[0];
    #pragma unroll
    for (int i = 1; i < 8; i++) M = fmaxf(M, s_m[i]);
    float ef[8]; float L = 0.f;
    #pragma unroll
    for (int i = 0; i < 8; i++) { ef[i] = __expf(s_m[i] - M); L += s_l[i] * ef[i]; }
    float invL = 1.f / L;
    for (int c = t; c < INDIM; c += 256) {
        float sum = 0.f;
        #pragma unroll
        for (int i = 0; i < 8; i++) sum = fmaf(s_part[i][c], ef[i], sum);
        g_acc[(size_t)b * INDIM + c] = sum * invL;
    }
}

// ---------------------------------------------------------------------------
// Kernel 4: epilogue. 128 blocks x 512 threads, GQ=8 queries per block.
// All layers coalesced warp-per-output with register-cached W rows.
// ---------------------------------------------------------------------------
__global__ void __launch_bounds__(512) k_epi(
    const float* __restrict__ Wv, const float* __restrict__ bv,
    const float* __restrict__ W1, const float* __restrict__ b1,
    const float* __restrict__ W2, const float* __restrict__ b2,
    float* __restrict__ out)
{
    int b0 = blockIdx.x * GQ;
    int t = threadIdx.x, lane = t & 31, w = t >> 5;
    __shared__ float acc[GQ][INDIM];
    __shared__ float z[GQ][FFNIN];
    __shared__ float h[GQ][LAT];

    for (int m = t; m < GQ * 96; m += 512) {
        int q = m / 96, c4 = m % 96;
        *(float4*)&acc[q][c4 * 4]     = *(const float4*)&g_acc[(size_t)(b0 + q) * INDIM + c4 * 4];
        *(float4*)&z[q][LAT + c4 * 4] = *(const float4*)&g_qin[(size_t)(b0 + q) * INDIM + c4 * 4];
    }
    __syncthreads();

    // z[:, :128] = Wv @ acc + bv
    for (int oi = 0; oi < 8; oi++) {
        int o = w * 8 + oi;
        const float* wr = Wv + (size_t)o * INDIM;
        float wreg[12];
        #pragma unroll
        for (int r = 0; r < 12; r++) wreg[r] = wr[lane + 32 * r];
        float p[GQ];
        #pragma unroll
        for (int q = 0; q < GQ; q++) {
            float s = 0.f;
            #pragma unroll
            for (int r = 0; r < 12; r++) s = fmaf(wreg[r], acc[q][lane + 32 * r], s);
            #pragma unroll
            for (int off = 16; off; off >>= 1) s += __shfl_xor_sync(0xffffffffu, s, off);
            p[q] = s;
        }
        float val = p[0];
        #pragma unroll
        for (int q = 1; q < GQ; q++) if (lane == q) val = p[q];
        if (lane < GQ) z[lane][o] = val + bv[o];
    }
    __syncthreads();

    // h = relu(W1 @ z + b1)
    for (int oi = 0; oi < 8; oi++) {
        int o = w * 8 + oi;
        const float* wr = W1 + (size_t)o * FFNIN;
        float wreg[16];
        #pragma unroll
        for (int r = 0; r < 16; r++) wreg[r] = wr[lane + 32 * r];
        float p[GQ];
        #pragma unroll
        for (int q = 0; q < GQ; q++) {
            float s = 0.f;
            #pragma unroll
            for (int r = 0; r < 16; r++) s = fmaf(wreg[r], z[q][lane + 32 * r], s);
            #pragma unroll
            for (int off = 16; off; off >>= 1) s += __shfl_xor_sync(0xffffffffu, s, off);
            p[q] = s;
        }
        float val = p[0];
        #pragma unroll
        for (int q = 1; q < GQ; q++) if (lane == q) val = p[q];
        if (lane < GQ) h[lane][o] = fmaxf(val + b1[o], 0.f);
    }
    __syncthreads();

    // out = W2 @ h + b2
    for (int oi = 0; oi < 8; oi++) {
        int o = w * 8 + oi;
        const float* wr = W2 + (size_t)o * LAT;
        float wreg[4];
        #pragma unroll
        for (int r = 0; r < 4; r++) wreg[r] = wr[lane + 32 * r];
        float p[GQ];
        #pragma unroll
        for (int q = 0; q < GQ; q++) {
            float s = 0.f;
            #pragma unroll
            for (int r = 0; r < 4; r++) s = fmaf(wreg[r], h[q][lane + 32 * r], s);
            #pragma unroll
            for (int off = 16; off; off >>= 1) s += __shfl_xor_sync(0xffffffffu, s, off);
            p[q] = s;
        }
        float val = p[0];
        #pragma unroll
        for (int q = 1; q < GQ; q++) if (lane == q) val = p[q];
        if (lane < GQ) out[(size_t)(b0 + lane) * LAT + o] = val + b2[o];
    }
}

// ---------------------------------------------------------------------------
extern "C" void kernel_launch(void* const* d_in, const int* in_sizes, int n_in,
                              void* d_out, int out_size)
{
    const float* x    = (const float*)d_in[0];
    const float* mem  = (const float*)d_in[1];
    const float* dt   = (const float*)d_in[2];
    const float* tart = (const float*)d_in[3];
    const unsigned char* mask = (const unsigned char*)d_in[4];
    const int*   tidx = (const int*)d_in[5];
    const float* Wq = (const float*)d_in[6];
    const float* bq = (const float*)d_in[7];
    const float* Wk = (const float*)d_in[8];
    const float* bk = (const float*)d_in[9];
    const float* Wv = (const float*)d_in[10];
    const float* bv = (const float*)d_in[11];
    const float* W1 = (const float*)d_in[12];
    const float* b1 = (const float*)d_in[13];
    const float* W2 = (const float*)d_in[14];
    const float* b2 = (const float*)d_in[15];
    float* out = (float*)d_out;

    k_sig_zero<<<1, 32>>>();
    k_sig_probe<<<128, 256>>>((const unsigned*)mask);
    k_prep<<<BB / GQ, 512>>>(x, mem, tart, tidx, Wq, bq, Wk, bk);
    k_scan<<<BB, 256>>>(mask, tidx);
    k_gather<<<BB, 256>>>(x, mem, dt);
    k_epi<<<BB / GQ, 512>>>(Wv, bv, W1, b1, W2, b2, out);
}

// round 4
// speedup vs baseline: 4.9400x; 1.0404x over previous
#include <cuda_runtime.h>
#include <math.h>

// Problem constants (fixed shapes per reference)
#define NN 100000
#define BB 1024
#define LAT 128
#define INDIM 384      // NODE_DIM + 2*LATENT
#define FFNIN 512      // LATENT + IN_DIM
#define CAP 512        // neighbor list capacity (mean ~50)
#define GQ 8           // queries per block in prep/epi

// Scratch (device globals; no allocation allowed)
__device__ float g_qin[BB * INDIM];
__device__ float g_qk[BB * INDIM];
__device__ float g_qbias[BB];
__device__ float g_acc[BB * INDIM];
__device__ unsigned g_sig[4];

// ---------------------------------------------------------------------------
// Mask-dtype probe
// ---------------------------------------------------------------------------
__global__ void k_sig_zero() {
    if (threadIdx.x < 4) g_sig[threadIdx.x] = 0u;
}

__global__ void __launch_bounds__(256) k_sig_probe(const unsigned* __restrict__ w)
{
    unsigned c0 = 0, c1 = 0, c2 = 0, c3 = 0;
    int stride = gridDim.x * blockDim.x;
    for (int i = blockIdx.x * blockDim.x + threadIdx.x; i < (1 << 20); i += stride) {
        unsigned v = w[i];
        if (v == 0u) continue;
        c0 += (v == 0x3F800000u);
        c1 += (v == 0x00003F80u);
        c2 += (v == 0x00000001u);
        #pragma unroll
        for (int bb = 0; bb < 4; bb++) c3 += (((v >> (bb * 8)) & 0xFFu) == 0x01u);
    }
    #pragma unroll
    for (int o = 16; o; o >>= 1) {
        c0 += __shfl_down_sync(0xffffffffu, c0, o);
        c1 += __shfl_down_sync(0xffffffffu, c1, o);
        c2 += __shfl_down_sync(0xffffffffu, c2, o);
        c3 += __shfl_down_sync(0xffffffffu, c3, o);
    }
    if ((threadIdx.x & 31) == 0) {
        if (c0) atomicAdd(&g_sig[0], c0);
        if (c1) atomicAdd(&g_sig[1], c1);
        if (c2) atomicAdd(&g_sig[2], c2);
        if (c3) atomicAdd(&g_sig[3], c3);
    }
}

// ---------------------------------------------------------------------------
// Kernel 1: prep. 128 blocks x 512 threads, GQ=8 queries per block.
// ---------------------------------------------------------------------------
__global__ void __launch_bounds__(512) k_prep(
    const float* __restrict__ x, const float* __restrict__ mem,
    const float* __restrict__ tart, const int* __restrict__ tidx,
    const float* __restrict__ Wq, const float* __restrict__ bq,
    const float* __restrict__ Wk, const float* __restrict__ bk)
{
    int b0 = blockIdx.x * GQ;
    int t = threadIdx.x, lane = t & 31, w = t >> 5;
    __shared__ float qin[GQ][INDIM];
    __shared__ float qsm[GQ][LAT];
    __shared__ float wk_sm[16][INDIM];
    __shared__ int sidx[GQ];

    if (t < GQ) sidx[t] = tidx[b0 + t];
    __syncthreads();

    for (int m = t; m < GQ * 96; m += 512) {
        int q = m / 96, c4 = m % 96;
        float4 v;
        if (c4 < 32)      v = ((const float4*)(x    + (size_t)sidx[q] * LAT))[c4];
        else if (c4 < 64) v = ((const float4*)(mem  + (size_t)sidx[q] * LAT))[c4 - 32];
        else              v = ((const float4*)(tart + (size_t)(b0 + q) * LAT))[c4 - 64];
        *(float4*)&qin[q][c4 * 4] = v;
        *(float4*)&g_qin[(size_t)(b0 + q) * INDIM + c4 * 4] = v;
    }
    __syncthreads();

    // q = Wq @ qin + bq
    for (int oi = 0; oi < 8; oi++) {
        int o = w * 8 + oi;
        const float* wr = Wq + (size_t)o * INDIM;
        float wreg[12];
        #pragma unroll
        for (int r = 0; r < 12; r++) wreg[r] = wr[lane + 32 * r];
        float p[GQ];
        #pragma unroll
        for (int q = 0; q < GQ; q++) {
            float s = 0.f;
            #pragma unroll
            for (int r = 0; r < 12; r++) s = fmaf(wreg[r], qin[q][lane + 32 * r], s);
            #pragma unroll
            for (int off = 16; off; off >>= 1) s += __shfl_xor_sync(0xffffffffu, s, off);
            p[q] = s;
        }
        float val = p[0];
        #pragma unroll
        for (int q = 1; q < GQ; q++) if (lane == q) val = p[q];
        if (lane < GQ) qsm[lane][o] = val + bq[o];
    }
    __syncthreads();

    // qbias[q] = q . bk
    if (w < GQ) {
        float v = 0.f;
        #pragma unroll
        for (int r = 0; r < 4; r++) v = fmaf(qsm[w][lane + 32 * r], bk[lane + 32 * r], v);
        #pragma unroll
        for (int off = 16; off; off >>= 1) v += __shfl_xor_sync(0xffffffffu, v, off);
        if (lane == 0) g_qbias[b0 + w] = v;
    }

    // qk = Wk^T q
    float acc[GQ];
    #pragma unroll
    for (int q = 0; q < GQ; q++) acc[q] = 0.f;
    for (int j0 = 0; j0 < LAT; j0 += 16) {
        __syncthreads();
        for (int m = t; m < 16 * 96; m += 512) {
            int jj = m / 96, c4 = m % 96;
            *(float4*)&wk_sm[jj][c4 * 4] =
                ((const float4*)(Wk + (size_t)(j0 + jj) * INDIM))[c4];
        }
        __syncthreads();
        if (t < INDIM) {
            #pragma unroll
            for (int jj = 0; jj < 16; jj++) {
                float wv = wk_sm[jj][t];
                #pragma unroll
                for (int q = 0; q < GQ; q++) acc[q] = fmaf(qsm[q][j0 + jj], wv, acc[q]);
            }
        }
    }
    if (t < INDIM) {
        #pragma unroll
        for (int q = 0; q < GQ; q++) g_qk[(size_t)(b0 + q) * INDIM + t] = acc[q];
    }
}

// ---------------------------------------------------------------------------
// Kernel 2: FUSED scan + online-softmax gather. 1024 blocks x 256 thr.
// Phase 1: vectorized mask scan -> smem neighbor list (unroll-8, MLP 8)
// Phase 2: pipelined gather, each row loaded once, online softmax
// ---------------------------------------------------------------------------
#define PROC4(u, base) \
    if (u.x | u.y | u.z | u.w) { \
        if (u.x) { int sl = atomicAdd(&s_cnt, 1); if (sl < CAP) s_idx[sl] = (base) * 4 + 0; } \
        if (u.y) { int sl = atomicAdd(&s_cnt, 1); if (sl < CAP) s_idx[sl] = (base) * 4 + 1; } \
        if (u.z) { int sl = atomicAdd(&s_cnt, 1); if (sl < CAP) s_idx[sl] = (base) * 4 + 2; } \
        if (u.w) { int sl = atomicAdd(&s_cnt, 1); if (sl < CAP) s_idx[sl] = (base) * 4 + 3; } }

__global__ void __launch_bounds__(256) k_attn(
    const float* __restrict__ x, const float* __restrict__ mem,
    const float* __restrict__ dt, const unsigned char* __restrict__ maskb,
    const int* __restrict__ tidx)
{
    int b = blockIdx.x, t = threadIdx.x, lane = t & 31, w = t >> 5;
    __shared__ int   s_idx[CAP];
    __shared__ int   s_cnt;
    __shared__ float s_qk[INDIM];
    __shared__ float s_part[8][INDIM];
    __shared__ float s_m[8], s_l[8];

    if (t == 0) s_cnt = 0;
    for (int c = t; c < INDIM; c += 256) s_qk[c] = g_qk[(size_t)b * INDIM + c];

    unsigned c_f32 = g_sig[0], c_bf16 = g_sig[1], c_i32 = g_sig[2], c_u8 = g_sig[3];
    int mode = (c_bf16 > 0) ? 3 : (c_f32 > 0) ? 2 : (c_u8 > 2 * c_i32) ? 0 : 1;
    __syncthreads();

    // ---- Phase 1: mask scan ----
    if (mode == 1 || mode == 2) {                 // 4-byte elements
        const uint4* row = (const uint4*)(maskb + (size_t)b * NN * 4);
        const int NW = NN / 4;                    // 25000
        int i = t;
        for (; i + 1792 < NW; i += 2048) {
            uint4 a0 = row[i],        a1 = row[i + 256],  a2 = row[i + 512],  a3 = row[i + 768];
            uint4 a4 = row[i + 1024], a5 = row[i + 1280], a6 = row[i + 1536], a7 = row[i + 1792];
            PROC4(a0, i)        PROC4(a1, i + 256)  PROC4(a2, i + 512)  PROC4(a3, i + 768)
            PROC4(a4, i + 1024) PROC4(a5, i + 1280) PROC4(a6, i + 1536) PROC4(a7, i + 1792)
        }
        for (; i < NW; i += 256) { uint4 u = row[i]; PROC4(u, i) }
    } else if (mode == 0) {                       // u8
        const uint4* row = (const uint4*)(maskb + (size_t)b * NN);
        for (int i = t; i < NN / 16; i += 256) {
            uint4 u = row[i];
            if (u.x | u.y | u.z | u.w) {
                unsigned vals[4] = {u.x, u.y, u.z, u.w};
                #pragma unroll
                for (int k2 = 0; k2 < 4; k2++) {
                    unsigned v = vals[k2];
                    if (!v) continue;
                    #pragma unroll
                    for (int bb = 0; bb < 4; bb++) {
                        if ((v >> (bb * 8)) & 0xFFu) {
                            int sl = atomicAdd(&s_cnt, 1);
                            if (sl < CAP) s_idx[sl] = i * 16 + k2 * 4 + bb;
                        }
                    }
                }
            }
        }
    } else {                                      // bf16
        const uint4* row = (const uint4*)(maskb + (size_t)b * NN * 2);
        for (int i = t; i < NN / 8; i += 256) {
            uint4 u = row[i];
            if (u.x | u.y | u.z | u.w) {
                unsigned vals[4] = {u.x, u.y, u.z, u.w};
                #pragma unroll
                for (int k2 = 0; k2 < 4; k2++) {
                    unsigned v = vals[k2];
                    if (v & 0xFFFFu) { int sl = atomicAdd(&s_cnt, 1); if (sl < CAP) s_idx[sl] = i * 8 + k2 * 2; }
                    if (v >> 16)     { int sl = atomicAdd(&s_cnt, 1); if (sl < CAP) s_idx[sl] = i * 8 + k2 * 2 + 1; }
                }
            }
        }
    }
    __syncthreads();
    if (s_cnt == 0 && t == 0) { s_idx[0] = tidx[b]; s_cnt = 1; }
    __syncthreads();
    int cnt = min(s_cnt, CAP);

    // ---- Phase 2: pipelined single-pass online-softmax gather ----
    float qb = g_qbias[b];
    const float scale = 0.08838834764831845f;   // 1/sqrt(128)
    float m = -INFINITY, l = 0.f;
    float racc[12];
    #pragma unroll
    for (int r = 0; r < 12; r++) racc[r] = 0.f;

    int p = w;
    float rowv[12];
    if (p < cnt) {
        int n = s_idx[p];
        const float* px = x + (size_t)n * LAT;
        const float* pm = mem + (size_t)n * LAT;
        const float* pd = dt + (size_t)n * LAT;
        #pragma unroll
        for (int r = 0; r < 4; r++) rowv[r]     = px[lane + 32 * r];
        #pragma unroll
        for (int r = 0; r < 4; r++) rowv[4 + r] = pm[lane + 32 * r];
        #pragma unroll
        for (int r = 0; r < 4; r++) rowv[8 + r] = pd[lane + 32 * r];
    }
    while (p < cnt) {
        int pn = p + 8;
        float rnext[12];
        if (pn < cnt) {                       // prefetch next edge
            int n = s_idx[pn];
            const float* px = x + (size_t)n * LAT;
            const float* pm = mem + (size_t)n * LAT;
            const float* pd = dt + (size_t)n * LAT;
            #pragma unroll
            for (int r = 0; r < 4; r++) rnext[r]     = px[lane + 32 * r];
            #pragma unroll
            for (int r = 0; r < 4; r++) rnext[4 + r] = pm[lane + 32 * r];
            #pragma unroll
            for (int r = 0; r < 4; r++) rnext[8 + r] = pd[lane + 32 * r];
        }
        float dot = 0.f;
        #pragma unroll
        for (int r = 0; r < 12; r++) dot = fmaf(rowv[r], s_qk[32 * r + lane], dot);
        #pragma unroll
        for (int off = 16; off; off >>= 1) dot += __shfl_xor_sync(0xffffffffu, dot, off);
        float s = (dot + qb) * scale;
        float mnew = fmaxf(m, s);
        float corr = __expf(m - mnew);
        float e = __expf(s - mnew);
        l = l * corr + e;
        m = mnew;
        #pragma unroll
        for (int r = 0; r < 12; r++) racc[r] = fmaf(racc[r], corr, e * rowv[r]);
        #pragma unroll
        for (int r = 0; r < 12; r++) rowv[r] = rnext[r];
        p = pn;
    }
    #pragma unroll
    for (int r = 0; r < 12; r++) s_part[w][32 * r + lane] = racc[r];
    if (lane == 0) { s_m[w] = m; s_l[w] = l; }
    __syncthreads();

    // merge 8 warp-local online-softmax states
    float M = s_m[0];
    #pragma unroll
    for (int i = 1; i < 8; i++) M = fmaxf(M, s_m[i]);
    float ef[8]; float L = 0.f;
    #pragma unroll
    for (int i = 0; i < 8; i++) { ef[i] = __expf(s_m[i] - M); L += s_l[i] * ef[i]; }
    float invL = 1.f / L;
    for (int c = t; c < INDIM; c += 256) {
        float sum = 0.f;
        #pragma unroll
        for (int i = 0; i < 8; i++) sum = fmaf(s_part[i][c], ef[i], sum);
        g_acc[(size_t)b * INDIM + c] = sum * invL;
    }
}

// ---------------------------------------------------------------------------
// Kernel 3: epilogue. 128 blocks x 512 threads, GQ=8 queries per block.
// ---------------------------------------------------------------------------
__global__ void __launch_bounds__(512) k_epi(
    const float* __restrict__ Wv, const float* __restrict__ bv,
    const float* __restrict__ W1, const float* __restrict__ b1,
    const float* __restrict__ W2, const float* __restrict__ b2,
    float* __restrict__ out)
{
    int b0 = blockIdx.x * GQ;
    int t = threadIdx.x, lane = t & 31, w = t >> 5;
    __shared__ float acc[GQ][INDIM];
    __shared__ float z[GQ][FFNIN];
    __shared__ float h[GQ][LAT];

    for (int m = t; m < GQ * 96; m += 512) {
        int q = m / 96, c4 = m % 96;
        *(float4*)&acc[q][c4 * 4]     = *(const float4*)&g_acc[(size_t)(b0 + q) * INDIM + c4 * 4];
        *(float4*)&z[q][LAT + c4 * 4] = *(const float4*)&g_qin[(size_t)(b0 + q) * INDIM + c4 * 4];
    }
    __syncthreads();

    for (int oi = 0; oi < 8; oi++) {
        int o = w * 8 + oi;
        const float* wr = Wv + (size_t)o * INDIM;
        float wreg[12];
        #pragma unroll
        for (int r = 0; r < 12; r++) wreg[r] = wr[lane + 32 * r];
        float p[GQ];
        #pragma unroll
        for (int q = 0; q < GQ; q++) {
            float s = 0.f;
            #pragma unroll
            for (int r = 0; r < 12; r++) s = fmaf(wreg[r], acc[q][lane + 32 * r], s);
            #pragma unroll
            for (int off = 16; off; off >>= 1) s += __shfl_xor_sync(0xffffffffu, s, off);
            p[q] = s;
        }
        float val = p[0];
        #pragma unroll
        for (int q = 1; q < GQ; q++) if (lane == q) val = p[q];
        if (lane < GQ) z[lane][o] = val + bv[o];
    }
    __syncthreads();

    for (int oi = 0; oi < 8; oi++) {
        int o = w * 8 + oi;
        const float* wr = W1 + (size_t)o * FFNIN;
        float wreg[16];
        #pragma unroll
        for (int r = 0; r < 16; r++) wreg[r] = wr[lane + 32 * r];
        float p[GQ];
        #pragma unroll
        for (int q = 0; q < GQ; q++) {
            float s = 0.f;
            #pragma unroll
            for (int r = 0; r < 16; r++) s = fmaf(wreg[r], z[q][lane + 32 * r], s);
            #pragma unroll
            for (int off = 16; off; off >>= 1) s += __shfl_xor_sync(0xffffffffu, s, off);
            p[q] = s;
        }
        float val = p[0];
        #pragma unroll
        for (int q = 1; q < GQ; q++) if (lane == q) val = p[q];
        if (lane < GQ) h[lane][o] = fmaxf(val + b1[o], 0.f);
    }
    __syncthreads();

    for (int oi = 0; oi < 8; oi++) {
        int o = w * 8 + oi;
        const float* wr = W2 + (size_t)o * LAT;
        float wreg[4];
        #pragma unroll
        for (int r = 0; r < 4; r++) wreg[r] = wr[lane + 32 * r];
        float p[GQ];
        #pragma unroll
        for (int q = 0; q < GQ; q++) {
            float s = 0.f;
            #pragma unroll
            for (int r = 0; r < 4; r++) s = fmaf(wreg[r], h[q][lane + 32 * r], s);
            #pragma unroll
            for (int off = 16; off; off >>= 1) s += __shfl_xor_sync(0xffffffffu, s, off);
            p[q] = s;
        }
        float val = p[0];
        #pragma unroll
        for (int q = 1; q < GQ; q++) if (lane == q) val = p[q];
        if (lane < GQ) out[(size_t)(b0 + lane) * LAT + o] = val + b2[o];
    }
}

// ---------------------------------------------------------------------------
extern "C" void kernel_launch(void* const* d_in, const int* in_sizes, int n_in,
                              void* d_out, int out_size)
{
    const float* x    = (const float*)d_in[0];
    const float* mem  = (const float*)d_in[1];
    const float* dt   = (const float*)d_in[2];
    const float* tart = (const float*)d_in[3];
    const unsigned char* mask = (const unsigned char*)d_in[4];
    const int*   tidx = (const int*)d_in[5];
    const float* Wq = (const float*)d_in[6];
    const float* bq = (const float*)d_in[7];
    const float* Wk = (const float*)d_in[8];
    const float* bk = (const float*)d_in[9];
    const float* Wv = (const float*)d_in[10];
    const float* bv = (const float*)d_in[11];
    const float* W1 = (const float*)d_in[12];
    const float* b1 = (const float*)d_in[13];
    const float* W2 = (const float*)d_in[14];
    const float* b2 = (const float*)d_in[15];
    float* out = (float*)d_out;

    k_sig_zero<<<1, 32>>>();
    k_sig_probe<<<128, 256>>>((const unsigned*)mask);
    k_prep<<<BB / GQ, 512>>>(x, mem, tart, tidx, Wq, bq, Wk, bk);
    k_attn<<<BB, 256>>>(x, mem, dt, mask, tidx);
    k_epi<<<BB / GQ, 512>>>(Wv, bv, W1, b1, W2, b2, out);
}

// round 5
// speedup vs baseline: 5.8876x; 1.1918x over previous
#include <cuda_runtime.h>
#include <math.h>

// Problem constants (fixed shapes per reference)
#define NN 100000
#define BB 1024
#define LAT 128
#define INDIM 384      // NODE_DIM + 2*LATENT
#define FFNIN 512      // LATENT + IN_DIM
#define CAP 512        // neighbor list capacity (mean ~50)
#define GQ 8           // queries per block in prep/epi

// Scratch (device globals; no allocation allowed)
__device__ float g_qin[BB * INDIM];
__device__ float g_qk[BB * INDIM];
__device__ float g_qbias[BB];
__device__ float g_acc[BB * INDIM];
__device__ int   g_list[BB * CAP];
__device__ int   g_cnt[BB];
__device__ unsigned g_sig[4];

// Merge two partial-sum arrays across xor-lane distance `bit`:
// result at lane l = full pair-sum of (bit set ? b : a) over lanes {l, l^bit}
__device__ __forceinline__ float mrg(float a, float b, int bit, int lane) {
    float keep = (lane & bit) ? b : a;
    float send = (lane & bit) ? a : b;
    return keep + __shfl_xor_sync(0xffffffffu, send, bit);
}

// ---------------------------------------------------------------------------
// Mask-dtype probe
// ---------------------------------------------------------------------------
__global__ void k_sig_zero() {
    if (threadIdx.x < 4) g_sig[threadIdx.x] = 0u;
}

__global__ void __launch_bounds__(256) k_sig_probe(const unsigned* __restrict__ w)
{
    unsigned c0 = 0, c1 = 0, c2 = 0, c3 = 0;
    int stride = gridDim.x * blockDim.x;
    for (int i = blockIdx.x * blockDim.x + threadIdx.x; i < (1 << 20); i += stride) {
        unsigned v = w[i];
        if (v == 0u) continue;
        c0 += (v == 0x3F800000u);
        c1 += (v == 0x00003F80u);
        c2 += (v == 0x00000001u);
        #pragma unroll
        for (int bb = 0; bb < 4; bb++) c3 += (((v >> (bb * 8)) & 0xFFu) == 0x01u);
    }
    #pragma unroll
    for (int o = 16; o; o >>= 1) {
        c0 += __shfl_down_sync(0xffffffffu, c0, o);
        c1 += __shfl_down_sync(0xffffffffu, c1, o);
        c2 += __shfl_down_sync(0xffffffffu, c2, o);
        c3 += __shfl_down_sync(0xffffffffu, c3, o);
    }
    if ((threadIdx.x & 31) == 0) {
        if (c0) atomicAdd(&g_sig[0], c0);
        if (c1) atomicAdd(&g_sig[1], c1);
        if (c2) atomicAdd(&g_sig[2], c2);
        if (c3) atomicAdd(&g_sig[3], c3);
    }
}

// ---------------------------------------------------------------------------
// Kernel 1: prep. 128 blocks x 512 threads (runs on side stream, under scan).
// ---------------------------------------------------------------------------
__global__ void __launch_bounds__(512) k_prep(
    const float* __restrict__ x, const float* __restrict__ mem,
    const float* __restrict__ tart, const int* __restrict__ tidx,
    const float* __restrict__ Wq, const float* __restrict__ bq,
    const float* __restrict__ Wk, const float* __restrict__ bk)
{
    int b0 = blockIdx.x * GQ;
    int t = threadIdx.x, lane = t & 31, w = t >> 5;
    __shared__ float qin[GQ][INDIM];
    __shared__ float qsm[GQ][LAT];
    __shared__ float wk_sm[16][INDIM];
    __shared__ int sidx[GQ];

    if (t < GQ) sidx[t] = tidx[b0 + t];
    __syncthreads();

    for (int m = t; m < GQ * 96; m += 512) {
        int q = m / 96, c4 = m % 96;
        float4 v;
        if (c4 < 32)      v = ((const float4*)(x    + (size_t)sidx[q] * LAT))[c4];
        else if (c4 < 64) v = ((const float4*)(mem  + (size_t)sidx[q] * LAT))[c4 - 32];
        else              v = ((const float4*)(tart + (size_t)(b0 + q) * LAT))[c4 - 64];
        *(float4*)&qin[q][c4 * 4] = v;
        *(float4*)&g_qin[(size_t)(b0 + q) * INDIM + c4 * 4] = v;
    }
    __syncthreads();

    // q = Wq @ qin + bq  (warp-per-output, multi-reduce: 5 shuffles for 8 queries)
    for (int oi = 0; oi < 8; oi++) {
        int o = (w & 15) * 8 + oi;
        const float* wr = Wq + (size_t)o * INDIM;
        float wreg[12];
        #pragma unroll
        for (int r = 0; r < 12; r++) wreg[r] = wr[lane + 32 * r];
        float p[GQ];
        #pragma unroll
        for (int q = 0; q < GQ; q++) {
            float s = 0.f;
            #pragma unroll
            for (int r = 0; r < 12; r++) s = fmaf(wreg[r], qin[q][lane + 32 * r], s);
            p[q] = s;
        }
        float a0 = mrg(p[0], p[1], 16, lane), a1 = mrg(p[2], p[3], 16, lane);
        float a2 = mrg(p[4], p[5], 16, lane), a3 = mrg(p[6], p[7], 16, lane);
        float b4 = mrg(a0, a1, 8, lane), b5 = mrg(a2, a3, 8, lane);
        float c0 = mrg(b4, b5, 4, lane);
        c0 += __shfl_xor_sync(0xffffffffu, c0, 1);
        c0 += __shfl_xor_sync(0xffffffffu, c0, 2);
        float bias = bq[o];
        if ((lane & 3) == 0) {
            int q = ((lane >> 4) & 1) + ((lane >> 2) & 2) + (lane & 4);
            qsm[q][o] = c0 + bias;
        }
    }
    __syncthreads();

    // qbias[q] = q . bk
    if (w < GQ) {
        float v = 0.f;
        #pragma unroll
        for (int r = 0; r < 4; r++) v = fmaf(qsm[w][lane + 32 * r], bk[lane + 32 * r], v);
        #pragma unroll
        for (int off = 16; off; off >>= 1) v += __shfl_xor_sync(0xffffffffu, v, off);
        if (lane == 0) g_qbias[b0 + w] = v;
    }

    // qk = Wk^T q  (smem-staged Wk tiles)
    float acc[GQ];
    #pragma unroll
    for (int q = 0; q < GQ; q++) acc[q] = 0.f;
    for (int j0 = 0; j0 < LAT; j0 += 16) {
        __syncthreads();
        for (int m = t; m < 16 * 96; m += 512) {
            int jj = m / 96, c4 = m % 96;
            *(float4*)&wk_sm[jj][c4 * 4] =
                ((const float4*)(Wk + (size_t)(j0 + jj) * INDIM))[c4];
        }
        __syncthreads();
        if (t < INDIM) {
            #pragma unroll
            for (int jj = 0; jj < 16; jj++) {
                float wv = wk_sm[jj][t];
                #pragma unroll
                for (int q = 0; q < GQ; q++) acc[q] = fmaf(qsm[q][j0 + jj], wv, acc[q]);
            }
        }
    }
    if (t < INDIM) {
        #pragma unroll
        for (int q = 0; q < GQ; q++) g_qk[(size_t)(b0 + q) * INDIM + t] = acc[q];
    }
}

// ---------------------------------------------------------------------------
// Kernel 2: mask scan -> edge lists. 1024 blocks x 256 thr (R3 version: 78% DRAM).
// ---------------------------------------------------------------------------
#define PROC4(u, base) \
    if (u.x | u.y | u.z | u.w) { \
        if (u.x) { int sl = atomicAdd(&s_cnt, 1); if (sl < CAP) s_idx[sl] = (base) * 4 + 0; } \
        if (u.y) { int sl = atomicAdd(&s_cnt, 1); if (sl < CAP) s_idx[sl] = (base) * 4 + 1; } \
        if (u.z) { int sl = atomicAdd(&s_cnt, 1); if (sl < CAP) s_idx[sl] = (base) * 4 + 2; } \
        if (u.w) { int sl = atomicAdd(&s_cnt, 1); if (sl < CAP) s_idx[sl] = (base) * 4 + 3; } }

__global__ void __launch_bounds__(256) k_scan(
    const unsigned char* __restrict__ maskb, const int* __restrict__ tidx)
{
    int b = blockIdx.x, t = threadIdx.x;
    __shared__ int s_idx[CAP];
    __shared__ int s_cnt;
    if (t == 0) s_cnt = 0;
    unsigned c_f32 = g_sig[0], c_bf16 = g_sig[1], c_i32 = g_sig[2], c_u8 = g_sig[3];
    int mode = (c_bf16 > 0) ? 3 : (c_f32 > 0) ? 2 : (c_u8 > 2 * c_i32) ? 0 : 1;
    __syncthreads();

    if (mode == 1 || mode == 2) {                 // 4-byte elements
        const uint4* row = (const uint4*)(maskb + (size_t)b * NN * 4);
        const int NW = NN / 4;
        int i = t;
        for (; i + 768 < NW; i += 1024) {
            uint4 a = row[i], b4 = row[i + 256], c4 = row[i + 512], d4 = row[i + 768];
            PROC4(a, i) PROC4(b4, i + 256) PROC4(c4, i + 512) PROC4(d4, i + 768)
        }
        for (; i < NW; i += 256) { uint4 u = row[i]; PROC4(u, i) }
    } else if (mode == 0) {                       // u8
        const uint4* row = (const uint4*)(maskb + (size_t)b * NN);
        for (int i = t; i < NN / 16; i += 256) {
            uint4 u = row[i];
            if (u.x | u.y | u.z | u.w) {
                unsigned vals[4] = {u.x, u.y, u.z, u.w};
                #pragma unroll
                for (int k2 = 0; k2 < 4; k2++) {
                    unsigned v = vals[k2];
                    if (!v) continue;
                    #pragma unroll
                    for (int bb = 0; bb < 4; bb++) {
                        if ((v >> (bb * 8)) & 0xFFu) {
                            int sl = atomicAdd(&s_cnt, 1);
                            if (sl < CAP) s_idx[sl] = i * 16 + k2 * 4 + bb;
                        }
                    }
                }
            }
        }
    } else {                                      // bf16
        const uint4* row = (const uint4*)(maskb + (size_t)b * NN * 2);
        for (int i = t; i < NN / 8; i += 256) {
            uint4 u = row[i];
            if (u.x | u.y | u.z | u.w) {
                unsigned vals[4] = {u.x, u.y, u.z, u.w};
                #pragma unroll
                for (int k2 = 0; k2 < 4; k2++) {
                    unsigned v = vals[k2];
                    if (v & 0xFFFFu) { int sl = atomicAdd(&s_cnt, 1); if (sl < CAP) s_idx[sl] = i * 8 + k2 * 2; }
                    if (v >> 16)     { int sl = atomicAdd(&s_cnt, 1); if (sl < CAP) s_idx[sl] = i * 8 + k2 * 2 + 1; }
                }
            }
        }
    }
    __syncthreads();
    int cnt = min(s_cnt, CAP);
    if (cnt == 0) {
        if (t == 0) { g_list[b * CAP] = tidx[b]; g_cnt[b] = 1; }
        return;
    }
    for (int m = t; m < cnt; m += 256) g_list[b * CAP + m] = s_idx[m];
    if (t == 0) g_cnt[b] = cnt;
}

// ---------------------------------------------------------------------------
// Kernel 3: pipelined online-softmax gather. 1024 blocks x 512 thr (16 warps).
// ---------------------------------------------------------------------------
__global__ void __launch_bounds__(512) k_gather(
    const float* __restrict__ x, const float* __restrict__ mem,
    const float* __restrict__ dt)
{
    int b = blockIdx.x, t = threadIdx.x, lane = t & 31, w = t >> 5;
    __shared__ float s_qk[INDIM];
    __shared__ float s_part[16][INDIM];
    __shared__ float s_m[16], s_l[16];

    if (t < INDIM) s_qk[t] = g_qk[(size_t)b * INDIM + t];
    __syncthreads();
    int cnt = g_cnt[b];
    float qb = g_qbias[b];
    const float scale = 0.08838834764831845f;   // 1/sqrt(128)

    float m = -INFINITY, l = 0.f;
    float racc[12];
    #pragma unroll
    for (int r = 0; r < 12; r++) racc[r] = 0.f;

    int p = w;
    float rowv[12];
    if (p < cnt) {
        int n = g_list[b * CAP + p];
        const float* px = x + (size_t)n * LAT;
        const float* pm = mem + (size_t)n * LAT;
        const float* pd = dt + (size_t)n * LAT;
        #pragma unroll
        for (int r = 0; r < 4; r++) rowv[r]     = px[lane + 32 * r];
        #pragma unroll
        for (int r = 0; r < 4; r++) rowv[4 + r] = pm[lane + 32 * r];
        #pragma unroll
        for (int r = 0; r < 4; r++) rowv[8 + r] = pd[lane + 32 * r];
    }
    while (p < cnt) {
        int pn = p + 16;
        float rnext[12];
        if (pn < cnt) {
            int n = g_list[b * CAP + pn];
            const float* px = x + (size_t)n * LAT;
            const float* pm = mem + (size_t)n * LAT;
            const float* pd = dt + (size_t)n * LAT;
            #pragma unroll
            for (int r = 0; r < 4; r++) rnext[r]     = px[lane + 32 * r];
            #pragma unroll
            for (int r = 0; r < 4; r++) rnext[4 + r] = pm[lane + 32 * r];
            #pragma unroll
            for (int r = 0; r < 4; r++) rnext[8 + r] = pd[lane + 32 * r];
        }
        float dot = 0.f;
        #pragma unroll
        for (int r = 0; r < 12; r++) dot = fmaf(rowv[r], s_qk[32 * r + lane], dot);
        #pragma unroll
        for (int off = 16; off; off >>= 1) dot += __shfl_xor_sync(0xffffffffu, dot, off);
        float s = (dot + qb) * scale;
        float mnew = fmaxf(m, s);
        float corr = __expf(m - mnew);
        float e = __expf(s - mnew);
        l = l * corr + e;
        m = mnew;
        #pragma unroll
        for (int r = 0; r < 12; r++) racc[r] = fmaf(racc[r], corr, e * rowv[r]);
        #pragma unroll
        for (int r = 0; r < 12; r++) rowv[r] = rnext[r];
        p = pn;
    }
    #pragma unroll
    for (int r = 0; r < 12; r++) s_part[w][32 * r + lane] = racc[r];
    if (lane == 0) { s_m[w] = m; s_l[w] = l; }
    __syncthreads();

    // merge 16 warp-local online-softmax states
    float M = s_m[0];
    #pragma unroll
    for (int i = 1; i < 16; i++) M = fmaxf(M, s_m[i]);
    float L = 0.f;
    float ef[16];
    #pragma unroll
    for (int i = 0; i < 16; i++) { ef[i] = __expf(s_m[i] - M); L += s_l[i] * ef[i]; }
    float invL = 1.f / L;
    if (t < INDIM) {
        float sum = 0.f;
        #pragma unroll
        for (int i = 0; i < 16; i++) sum = fmaf(s_part[i][t], ef[i], sum);
        g_acc[(size_t)b * INDIM + t] = sum * invL;
    }
}

// ---------------------------------------------------------------------------
// Kernel 4: epilogue. 128 blocks x 512 threads. Multi-reduce GEMV stages.
// ---------------------------------------------------------------------------
__global__ void __launch_bounds__(512) k_epi(
    const float* __restrict__ Wv, const float* __restrict__ bv,
    const float* __restrict__ W1, const float* __restrict__ b1,
    const float* __restrict__ W2, const float* __restrict__ b2,
    float* __restrict__ out)
{
    int b0 = blockIdx.x * GQ;
    int t = threadIdx.x, lane = t & 31, w = t >> 5;
    __shared__ float acc[GQ][INDIM];
    __shared__ float z[GQ][FFNIN];
    __shared__ float h[GQ][LAT];

    for (int m = t; m < GQ * 96; m += 512) {
        int q = m / 96, c4 = m % 96;
        *(float4*)&acc[q][c4 * 4]     = *(const float4*)&g_acc[(size_t)(b0 + q) * INDIM + c4 * 4];
        *(float4*)&z[q][LAT + c4 * 4] = *(const float4*)&g_qin[(size_t)(b0 + q) * INDIM + c4 * 4];
    }
    __syncthreads();

    // z[:, :128] = Wv @ acc + bv
    for (int oi = 0; oi < 8; oi++) {
        int o = w * 8 + oi;
        const float* wr = Wv + (size_t)o * INDIM;
        float wreg[12];
        #pragma unroll
        for (int r = 0; r < 12; r++) wreg[r] = wr[lane + 32 * r];
        float p[GQ];
        #pragma unroll
        for (int q = 0; q < GQ; q++) {
            float s = 0.f;
            #pragma unroll
            for (int r = 0; r < 12; r++) s = fmaf(wreg[r], acc[q][lane + 32 * r], s);
            p[q] = s;
        }
        float a0 = mrg(p[0], p[1], 16, lane), a1 = mrg(p[2], p[3], 16, lane);
        float a2 = mrg(p[4], p[5], 16, lane), a3 = mrg(p[6], p[7], 16, lane);
        float b4 = mrg(a0, a1, 8, lane), b5 = mrg(a2, a3, 8, lane);
        float c0 = mrg(b4, b5, 4, lane);
        c0 += __shfl_xor_sync(0xffffffffu, c0, 1);
        c0 += __shfl_xor_sync(0xffffffffu, c0, 2);
        float bias = bv[o];
        if ((lane & 3) == 0) {
            int q = ((lane >> 4) & 1) + ((lane >> 2) & 2) + (lane & 4);
            z[q][o] = c0 + bias;
        }
    }
    __syncthreads();

    // h = relu(W1 @ z + b1)
    for (int oi = 0; oi < 8; oi++) {
        int o = w * 8 + oi;
        const float* wr = W1 + (size_t)o * FFNIN;
        float wreg[16];
        #pragma unroll
        for (int r = 0; r < 16; r++) wreg[r] = wr[lane + 32 * r];
        float p[GQ];
        #pragma unroll
        for (int q = 0; q < GQ; q++) {
            float s = 0.f;
            #pragma unroll
            for (int r = 0; r < 16; r++) s = fmaf(wreg[r], z[q][lane + 32 * r], s);
            p[q] = s;
        }
        float a0 = mrg(p[0], p[1], 16, lane), a1 = mrg(p[2], p[3], 16, lane);
        float a2 = mrg(p[4], p[5], 16, lane), a3 = mrg(p[6], p[7], 16, lane);
        float b4 = mrg(a0, a1, 8, lane), b5 = mrg(a2, a3, 8, lane);
        float c0 = mrg(b4, b5, 4, lane);
        c0 += __shfl_xor_sync(0xffffffffu, c0, 1);
        c0 += __shfl_xor_sync(0xffffffffu, c0, 2);
        float bias = b1[o];
        if ((lane & 3) == 0) {
            int q = ((lane >> 4) & 1) + ((lane >> 2) & 2) + (lane & 4);
            h[q][o] = fmaxf(c0 + bias, 0.f);
        }
    }
    __syncthreads();

    // out = W2 @ h + b2
    for (int oi = 0; oi < 8; oi++) {
        int o = w * 8 + oi;
        const float* wr = W2 + (size_t)o * LAT;
        float wreg[4];
        #pragma unroll
        for (int r = 0; r < 4; r++) wreg[r] = wr[lane + 32 * r];
        float p[GQ];
        #pragma unroll
        for (int q = 0; q < GQ; q++) {
            float s = 0.f;
            #pragma unroll
            for (int r = 0; r < 4; r++) s = fmaf(wreg[r], h[q][lane + 32 * r], s);
            p[q] = s;
        }
        float a0 = mrg(p[0], p[1], 16, lane), a1 = mrg(p[2], p[3], 16, lane);
        float a2 = mrg(p[4], p[5], 16, lane), a3 = mrg(p[6], p[7], 16, lane);
        float b4 = mrg(a0, a1, 8, lane), b5 = mrg(a2, a3, 8, lane);
        float c0 = mrg(b4, b5, 4, lane);
        c0 += __shfl_xor_sync(0xffffffffu, c0, 1);
        c0 += __shfl_xor_sync(0xffffffffu, c0, 2);
        float bias = b2[o];
        if ((lane & 3) == 0) {
            int q = ((lane >> 4) & 1) + ((lane >> 2) & 2) + (lane & 4);
            out[(size_t)(b0 + q) * LAT + o] = c0 + bias;
        }
    }
}

// ---------------------------------------------------------------------------
extern "C" void kernel_launch(void* const* d_in, const int* in_sizes, int n_in,
                              void* d_out, int out_size)
{
    const float* x    = (const float*)d_in[0];
    const float* mem  = (const float*)d_in[1];
    const float* dt   = (const float*)d_in[2];
    const float* tart = (const float*)d_in[3];
    const unsigned char* mask = (const unsigned char*)d_in[4];
    const int*   tidx = (const int*)d_in[5];
    const float* Wq = (const float*)d_in[6];
    const float* bq = (const float*)d_in[7];
    const float* Wk = (const float*)d_in[8];
    const float* bk = (const float*)d_in[9];
    const float* Wv = (const float*)d_in[10];
    const float* bv = (const float*)d_in[11];
    const float* W1 = (const float*)d_in[12];
    const float* b1 = (const float*)d_in[13];
    const float* W2 = (const float*)d_in[14];
    const float* b2 = (const float*)d_in[15];
    float* out = (float*)d_out;

    // Fork-join: prep (weights path) runs concurrently with probe+scan (mask path).
    static cudaStream_t s_side = nullptr;
    static cudaEvent_t e_fork = nullptr, e_join = nullptr;
    if (s_side == nullptr) {
        cudaStreamCreateWithFlags(&s_side, cudaStreamNonBlocking);
        cudaEventCreateWithFlags(&e_fork, cudaEventDisableTiming);
        cudaEventCreateWithFlags(&e_join, cudaEventDisableTiming);
    }

    cudaEventRecord(e_fork, 0);
    cudaStreamWaitEvent(s_side, e_fork, 0);
    k_prep<<<BB / GQ, 512, 0, s_side>>>(x, mem, tart, tidx, Wq, bq, Wk, bk);
    cudaEventRecord(e_join, s_side);

    k_sig_zero<<<1, 32>>>();
    k_sig_probe<<<128, 256>>>((const unsigned*)mask);
    k_scan<<<BB, 256>>>(mask, tidx);

    cudaStreamWaitEvent(0, e_join, 0);
    k_gather<<<BB, 512>>>(x, mem, dt);
    k_epi<<<BB / GQ, 512>>>(Wv, bv, W1, b1, W2, b2, out);
}